// round 1
// baseline (speedup 1.0000x reference)
#include <cuda_runtime.h>
#include <cuda_fp16.h>
#include <cuda_bf16.h>
#include <cstdint>

#define L_TOT 4096
#define HID   2560
#define NH    8
#define NKV   4
#define HD    256
#define SEQ   1024
#define QKV_W 4096   // 2048 q + 1024 k + 1024 v columns

// ---------------- device scratch (no dynamic alloc allowed) ----------------
__device__ __half g_Xh [L_TOT * HID];          // hidden in fp16
__device__ __half g_Wqh[HID * NH * HD];
__device__ __half g_Wkh[HID * NKV * HD];
__device__ __half g_Wvh[HID * NKV * HD];
__device__ __half g_Woh[NH * HD * HID];
__device__ float  g_qkv[L_TOT * QKV_W];        // fp32 pre-norm q|k|v
__device__ __half g_Q[(size_t)NH  * L_TOT * HD];  // [h][t][d], pre-scaled by 1/16
__device__ __half g_K[(size_t)NKV * L_TOT * HD];
__device__ __half g_V[(size_t)NKV * L_TOT * HD];
__device__ __half g_A[L_TOT * NH * HD];        // attention output [t][h*HD+d]

// ---------------- small PTX helpers ----------------
__device__ __forceinline__ uint32_t sptr(const void* p) {
    return static_cast<uint32_t>(__cvta_generic_to_shared(p));
}
__device__ __forceinline__ void ldsm_x4(uint32_t* r, const void* p) {
    uint32_t a = sptr(p);
    asm volatile("ldmatrix.sync.aligned.m8n8.x4.shared.b16 {%0,%1,%2,%3}, [%4];"
                 : "=r"(r[0]), "=r"(r[1]), "=r"(r[2]), "=r"(r[3]) : "r"(a));
}
__device__ __forceinline__ void ldsm_x4_t(uint32_t* r, const void* p) {
    uint32_t a = sptr(p);
    asm volatile("ldmatrix.sync.aligned.m8n8.x4.trans.shared.b16 {%0,%1,%2,%3}, [%4];"
                 : "=r"(r[0]), "=r"(r[1]), "=r"(r[2]), "=r"(r[3]) : "r"(a));
}
__device__ __forceinline__ void mma_16816(float* c, const uint32_t* a, const uint32_t* b) {
    asm volatile(
        "mma.sync.aligned.m16n8k16.row.col.f32.f16.f16.f32 "
        "{%0,%1,%2,%3}, {%4,%5,%6,%7}, {%8,%9}, {%0,%1,%2,%3};"
        : "+f"(c[0]), "+f"(c[1]), "+f"(c[2]), "+f"(c[3])
        : "r"(a[0]), "r"(a[1]), "r"(a[2]), "r"(a[3]), "r"(b[0]), "r"(b[1]));
}
__device__ __forceinline__ void cp16(void* s, const void* g) {
    uint32_t a = sptr(s);
    asm volatile("cp.async.cg.shared.global [%0], [%1], 16;" :: "r"(a), "l"(g));
}
__device__ __forceinline__ void cp_commit() { asm volatile("cp.async.commit_group;"); }
__device__ __forceinline__ void cp_wait0()  { asm volatile("cp.async.wait_group 0;"); }

__device__ __forceinline__ uint32_t packh2(float a, float b) {
    __half2 h = __floats2half2_rn(a, b);
    return *reinterpret_cast<uint32_t*>(&h);
}
__device__ __forceinline__ float qmax(float v) {
    v = fmaxf(v, __shfl_xor_sync(0xffffffffu, v, 1));
    v = fmaxf(v, __shfl_xor_sync(0xffffffffu, v, 2));
    return v;
}
__device__ __forceinline__ float qsum(float v) {
    v += __shfl_xor_sync(0xffffffffu, v, 1);
    v += __shfl_xor_sync(0xffffffffu, v, 2);
    return v;
}

// ---------------- fp32 -> fp16 convert (vectorized by 4) ----------------
__global__ void f2h4_kernel(const float4* __restrict__ src, __half2* __restrict__ dst, int n4) {
    int i = blockIdx.x * blockDim.x + threadIdx.x;
    if (i >= n4) return;
    float4 v = src[i];
    dst[2 * i]     = __floats2half2_rn(v.x, v.y);
    dst[2 * i + 1] = __floats2half2_rn(v.z, v.w);
}

// ---------------- generic fp16 GEMM: C(f32) = A(f16 MxK) * B(f16 KxN) ----------------
#define BM 128
#define BN 128
#define BK 32
#define PADA 8
#define PADB 8

__global__ __launch_bounds__(256) void gemm_f16f32(
    const __half* __restrict__ A, const __half* __restrict__ B,
    float* __restrict__ C, int M, int N, int K, int ldc)
{
    __shared__ __align__(16) __half As[2][BM][BK + PADA];
    __shared__ __align__(16) __half Bs[2][BK][BN + PADB];

    int tid = threadIdx.x;
    int warp = tid >> 5, lane = tid & 31;
    int wm = warp >> 2, wn = warp & 3;     // 2x4 warp grid, warp tile 64x32
    int bm = blockIdx.y * BM, bn = blockIdx.x * BN;

    float acc[4][4][4];
#pragma unroll
    for (int a = 0; a < 4; a++)
#pragma unroll
        for (int b = 0; b < 4; b++)
#pragma unroll
            for (int c = 0; c < 4; c++) acc[a][b][c] = 0.f;

    int nkt = K / BK;

    auto loadA = [&](int buf, int kt) {
#pragma unroll
        for (int i = 0; i < 2; i++) {
            int v = i * 256 + tid;
            int r = v >> 2, cv = v & 3;
            cp16(&As[buf][r][cv * 8], A + (size_t)(bm + r) * K + kt * BK + cv * 8);
        }
    };
    auto loadB = [&](int buf, int kt) {
#pragma unroll
        for (int i = 0; i < 2; i++) {
            int v = i * 256 + tid;
            int r = v >> 4, cv = v & 15;
            cp16(&Bs[buf][r][cv * 8], B + (size_t)(kt * BK + r) * N + bn + cv * 8);
        }
    };

    loadA(0, 0); loadB(0, 0); cp_commit();
    cp_wait0(); __syncthreads();

    int buf = 0;
    for (int kt = 0; kt < nkt; kt++) {
        if (kt + 1 < nkt) { loadA(buf ^ 1, kt + 1); loadB(buf ^ 1, kt + 1); cp_commit(); }
#pragma unroll
        for (int kk = 0; kk < 2; kk++) {
            uint32_t af[4][4];
#pragma unroll
            for (int mi = 0; mi < 4; mi++)
                ldsm_x4(af[mi], &As[buf][wm * 64 + mi * 16 + (lane & 15)][kk * 16 + (lane >> 4) * 8]);
            uint32_t bf[2][4];
#pragma unroll
            for (int g = 0; g < 2; g++)
                ldsm_x4_t(bf[g], &Bs[buf][kk * 16 + (lane & 15)][wn * 32 + g * 16 + (lane >> 4) * 8]);
#pragma unroll
            for (int mi = 0; mi < 4; mi++)
#pragma unroll
                for (int ni = 0; ni < 4; ni++)
                    mma_16816(acc[mi][ni], af[mi], &bf[ni >> 1][(ni & 1) * 2]);
        }
        if (kt + 1 < nkt) cp_wait0();
        __syncthreads();
        buf ^= 1;
    }

#pragma unroll
    for (int mi = 0; mi < 4; mi++)
#pragma unroll
        for (int ni = 0; ni < 4; ni++) {
            int r0 = bm + wm * 64 + mi * 16 + (lane >> 2);
            int c0 = bn + wn * 32 + ni * 8 + (lane & 3) * 2;
            float2 v0 = make_float2(acc[mi][ni][0], acc[mi][ni][1]);
            float2 v1 = make_float2(acc[mi][ni][2], acc[mi][ni][3]);
            *reinterpret_cast<float2*>(C + (size_t)r0 * ldc + c0)       = v0;
            *reinterpret_cast<float2*>(C + (size_t)(r0 + 8) * ldc + c0) = v1;
        }
}

// ---------------- RMSNorm + RoPE (warp per (token, head)) ----------------
__global__ __launch_bounds__(256) void normrope_kernel(
    const float* __restrict__ qkv, const float* __restrict__ cosb,
    const float* __restrict__ sinb, const float* __restrict__ qw,
    const float* __restrict__ kw)
{
    int gw = blockIdx.x * 8 + (threadIdx.x >> 5);
    int lane = threadIdx.x & 31;
    int t = gw / 12, hh = gw - t * 12;

    const float* src; const float* w; __half* dst; float sc;
    if (hh < 8) {
        src = qkv + (size_t)t * QKV_W + hh * HD;
        w = qw; dst = g_Q + ((size_t)hh * L_TOT + t) * HD;
        sc = 0.0625f;   // fold SCALING = 256^-0.5
    } else {
        int kvh = hh - 8;
        src = qkv + (size_t)t * QKV_W + 2048 + kvh * HD;
        w = kw; dst = g_K + ((size_t)kvh * L_TOT + t) * HD;
        sc = 1.0f;
    }

    int j = lane * 4;
    float4 x1 = *reinterpret_cast<const float4*>(src + j);
    float4 x2 = *reinterpret_cast<const float4*>(src + 128 + j);

    float ss = x1.x * x1.x + x1.y * x1.y + x1.z * x1.z + x1.w * x1.w
             + x2.x * x2.x + x2.y * x2.y + x2.z * x2.z + x2.w * x2.w;
#pragma unroll
    for (int o = 16; o; o >>= 1) ss += __shfl_xor_sync(0xffffffffu, ss, o);
    float r = rsqrtf(ss * (1.0f / 256.0f) + 1e-6f);

    float4 w1 = *reinterpret_cast<const float4*>(w + j);
    float4 w2 = *reinterpret_cast<const float4*>(w + 128 + j);
    float4 c1 = *reinterpret_cast<const float4*>(cosb + (size_t)t * HD + j);
    float4 c2 = *reinterpret_cast<const float4*>(cosb + (size_t)t * HD + 128 + j);
    float4 s1 = *reinterpret_cast<const float4*>(sinb + (size_t)t * HD + j);
    float4 s2 = *reinterpret_cast<const float4*>(sinb + (size_t)t * HD + 128 + j);

    float n1[4] = { x1.x * r * (1.f + w1.x), x1.y * r * (1.f + w1.y),
                    x1.z * r * (1.f + w1.z), x1.w * r * (1.f + w1.w) };
    float n2[4] = { x2.x * r * (1.f + w2.x), x2.y * r * (1.f + w2.y),
                    x2.z * r * (1.f + w2.z), x2.w * r * (1.f + w2.w) };
    float cA[4] = { c1.x, c1.y, c1.z, c1.w }, cB[4] = { c2.x, c2.y, c2.z, c2.w };
    float sA[4] = { s1.x, s1.y, s1.z, s1.w }, sB[4] = { s2.x, s2.y, s2.z, s2.w };

    __half2 o1[2], o2[2];
#pragma unroll
    for (int i = 0; i < 4; i++) {
        float lo = (n1[i] * cA[i] - n2[i] * sA[i]) * sc;   // d = j+i
        float hi = (n2[i] * cB[i] + n1[i] * sB[i]) * sc;   // d = j+i+128
        reinterpret_cast<__half*>(o1)[i] = __float2half_rn(lo);
        reinterpret_cast<__half*>(o2)[i] = __float2half_rn(hi);
    }
    *reinterpret_cast<__half2*>(dst + j)       = o1[0];
    *reinterpret_cast<__half2*>(dst + j + 2)   = o1[1];
    *reinterpret_cast<__half2*>(dst + 128 + j)     = o2[0];
    *reinterpret_cast<__half2*>(dst + 128 + j + 2) = o2[1];
}

// ---------------- V convert fp32 -> fp16 head-major ----------------
__global__ void vconv_kernel(const float* __restrict__ qkv) {
    int i = blockIdx.x * blockDim.x + threadIdx.x;   // over L_TOT*512 half2
    if (i >= L_TOT * 512) return;
    int t = i >> 9, c = (i & 511) * 2;
    int kvh = c >> 8, d = c & 255;
    float2 v = *reinterpret_cast<const float2*>(qkv + (size_t)t * QKV_W + 3072 + c);
    *reinterpret_cast<__half2*>(g_V + ((size_t)kvh * L_TOT + t) * HD + d) =
        __floats2half2_rn(v.x, v.y);
}

// ---------------- flash attention: CTA = (qtile, seq, head), 4 warps ----------------
#define SMEM_ATTN (3 * 64 * 264 * 2)

__global__ __launch_bounds__(128) void attn_kernel() {
    extern __shared__ __half sm[];
    __half* sQ = sm;                  // [64][264]
    __half* sK = sm + 64 * 264;
    __half* sV = sm + 2 * 64 * 264;

    int tid = threadIdx.x, warp = tid >> 5, lane = tid & 31;
    int qt = blockIdx.x, seq = blockIdx.y, h = blockIdx.z;
    int kvh = h >> 1;

    const __half* Qg = g_Q + ((size_t)h * L_TOT + seq * SEQ + qt * 64) * HD;
    const __half* Kg = g_K + ((size_t)kvh * L_TOT + seq * SEQ) * HD;
    const __half* Vg = g_V + ((size_t)kvh * L_TOT + seq * SEQ) * HD;

    // Q tile load (own cp.async group; absorbed by first wait in loop)
#pragma unroll
    for (int i = 0; i < 16; i++) {
        int v = i * 128 + tid, r = v >> 5, cv = v & 31;
        cp16(&sQ[r * 264 + cv * 8], Qg + (size_t)r * HD + cv * 8);
    }
    cp_commit();

    float o[32][4];
#pragma unroll
    for (int nt = 0; nt < 32; nt++)
#pragma unroll
        for (int c = 0; c < 4; c++) o[nt][c] = 0.f;
    float m0 = -1e30f, m1 = -1e30f, l0 = 0.f, l1 = 0.f;

    for (int kt = 0; kt <= qt; kt++) {
#pragma unroll
        for (int i = 0; i < 16; i++) {
            int v = i * 128 + tid, r = v >> 5, cv = v & 31;
            cp16(&sK[r * 264 + cv * 8], Kg + (size_t)(kt * 64 + r) * HD + cv * 8);
            cp16(&sV[r * 264 + cv * 8], Vg + (size_t)(kt * 64 + r) * HD + cv * 8);
        }
        cp_commit(); cp_wait0(); __syncthreads();

        // S = Q K^T  (warp: 16 rows x 64 cols)
        float s[8][4];
#pragma unroll
        for (int nt = 0; nt < 8; nt++)
#pragma unroll
            for (int c = 0; c < 4; c++) s[nt][c] = 0.f;

#pragma unroll
        for (int kc = 0; kc < 16; kc++) {
            uint32_t af[4];
            ldsm_x4(af, &sQ[(warp * 16 + (lane & 15)) * 264 + kc * 16 + (lane >> 4) * 8]);
#pragma unroll
            for (int g = 0; g < 4; g++) {
                uint32_t bf[4];
                ldsm_x4(bf, &sK[(g * 16 + (lane & 15)) * 264 + kc * 16 + (lane >> 4) * 8]);
                uint32_t b0[2] = { bf[0], bf[2] };
                uint32_t b1[2] = { bf[1], bf[3] };
                mma_16816(s[2 * g],     af, b0);
                mma_16816(s[2 * g + 1], af, b1);
            }
        }

        if (kt == qt) {     // causal mask on diagonal tile
            int r0 = warp * 16 + (lane >> 2);
#pragma unroll
            for (int nt = 0; nt < 8; nt++) {
                int c = nt * 8 + (lane & 3) * 2;
                if (c     > r0)     s[nt][0] = -1e30f;
                if (c + 1 > r0)     s[nt][1] = -1e30f;
                if (c     > r0 + 8) s[nt][2] = -1e30f;
                if (c + 1 > r0 + 8) s[nt][3] = -1e30f;
            }
        }

        // online softmax
        float mx0 = -1e30f, mx1 = -1e30f;
#pragma unroll
        for (int nt = 0; nt < 8; nt++) {
            mx0 = fmaxf(mx0, fmaxf(s[nt][0], s[nt][1]));
            mx1 = fmaxf(mx1, fmaxf(s[nt][2], s[nt][3]));
        }
        mx0 = qmax(mx0); mx1 = qmax(mx1);
        float nm0 = fmaxf(m0, mx0), nm1 = fmaxf(m1, mx1);
        float a0 = __expf(m0 - nm0), a1 = __expf(m1 - nm1);
        float sum0 = 0.f, sum1 = 0.f;
#pragma unroll
        for (int nt = 0; nt < 8; nt++) {
            s[nt][0] = __expf(s[nt][0] - nm0);
            s[nt][1] = __expf(s[nt][1] - nm0);
            s[nt][2] = __expf(s[nt][2] - nm1);
            s[nt][3] = __expf(s[nt][3] - nm1);
            sum0 += s[nt][0] + s[nt][1];
            sum1 += s[nt][2] + s[nt][3];
        }
        sum0 = qsum(sum0); sum1 = qsum(sum1);
        l0 = l0 * a0 + sum0; l1 = l1 * a1 + sum1;
        m0 = nm0; m1 = nm1;
#pragma unroll
        for (int nt = 0; nt < 32; nt++) {
            o[nt][0] *= a0; o[nt][1] *= a0;
            o[nt][2] *= a1; o[nt][3] *= a1;
        }

        // O += P V
#pragma unroll
        for (int j = 0; j < 4; j++) {
            uint32_t af2[4];
            af2[0] = packh2(s[2 * j][0],     s[2 * j][1]);
            af2[1] = packh2(s[2 * j][2],     s[2 * j][3]);
            af2[2] = packh2(s[2 * j + 1][0], s[2 * j + 1][1]);
            af2[3] = packh2(s[2 * j + 1][2], s[2 * j + 1][3]);
#pragma unroll
            for (int g = 0; g < 16; g++) {
                uint32_t bf[4];
                ldsm_x4_t(bf, &sV[(j * 16 + (lane & 15)) * 264 + g * 16 + (lane >> 4) * 8]);
                mma_16816(o[2 * g],     af2, &bf[0]);
                mma_16816(o[2 * g + 1], af2, &bf[2]);
            }
        }
        __syncthreads();
    }

    float i0 = 1.f / l0, i1 = 1.f / l1;
    int row = seq * SEQ + qt * 64 + warp * 16 + (lane >> 2);
    __half* Ob0 = g_A + (size_t)row * (NH * HD) + h * HD;
    __half* Ob1 = g_A + (size_t)(row + 8) * (NH * HD) + h * HD;
#pragma unroll
    for (int nt = 0; nt < 32; nt++) {
        int c = nt * 8 + (lane & 3) * 2;
        *reinterpret_cast<__half2*>(Ob0 + c) = __floats2half2_rn(o[nt][0] * i0, o[nt][1] * i0);
        *reinterpret_cast<__half2*>(Ob1 + c) = __floats2half2_rn(o[nt][2] * i1, o[nt][3] * i1);
    }
}

// ---------------- launch ----------------
extern "C" void kernel_launch(void* const* d_in, const int* in_sizes, int n_in,
                              void* d_out, int out_size) {
    const float* X    = (const float*)d_in[0];
    const float* cosb = (const float*)d_in[1];
    const float* sinb = (const float*)d_in[2];
    const float* Wq   = (const float*)d_in[3];
    const float* Wk   = (const float*)d_in[4];
    const float* Wv   = (const float*)d_in[5];
    const float* Wo   = (const float*)d_in[6];
    const float* qw   = (const float*)d_in[7];
    const float* kw   = (const float*)d_in[8];
    float* out = (float*)d_out;

    void *pXh, *pWq, *pWk, *pWv, *pWo, *pqkv, *pQ, *pK, *pV, *pA;
    cudaGetSymbolAddress(&pXh,  g_Xh);
    cudaGetSymbolAddress(&pWq,  g_Wqh);
    cudaGetSymbolAddress(&pWk,  g_Wkh);
    cudaGetSymbolAddress(&pWv,  g_Wvh);
    cudaGetSymbolAddress(&pWo,  g_Woh);
    cudaGetSymbolAddress(&pqkv, g_qkv);
    cudaGetSymbolAddress(&pQ,   g_Q);
    cudaGetSymbolAddress(&pK,   g_K);
    cudaGetSymbolAddress(&pV,   g_V);
    cudaGetSymbolAddress(&pA,   g_A);

    auto conv = [&](const float* src, void* dst, int n) {
        int n4 = n / 4;
        f2h4_kernel<<<(n4 + 255) / 256, 256>>>(
            (const float4*)src, (__half2*)dst, n4);
    };
    conv(X,  pXh, L_TOT * HID);
    conv(Wq, pWq, HID * NH * HD);
    conv(Wk, pWk, HID * NKV * HD);
    conv(Wv, pWv, HID * NKV * HD);
    conv(Wo, pWo, NH * HD * HID);

    // QKV projections into fp32 scratch (columns 0..2047 | 2048..3071 | 3072..4095)
    gemm_f16f32<<<dim3(2048 / BN, L_TOT / BM), 256>>>(
        (const __half*)pXh, (const __half*)pWq, (float*)pqkv, L_TOT, 2048, HID, QKV_W);
    gemm_f16f32<<<dim3(1024 / BN, L_TOT / BM), 256>>>(
        (const __half*)pXh, (const __half*)pWk, (float*)pqkv + 2048, L_TOT, 1024, HID, QKV_W);
    gemm_f16f32<<<dim3(1024 / BN, L_TOT / BM), 256>>>(
        (const __half*)pXh, (const __half*)pWv, (float*)pqkv + 3072, L_TOT, 1024, HID, QKV_W);

    normrope_kernel<<<L_TOT * 12 / 8, 256>>>((const float*)pqkv, cosb, sinb, qw, kw);
    vconv_kernel<<<(L_TOT * 512 + 255) / 256, 256>>>((const float*)pqkv);

    cudaFuncSetAttribute(attn_kernel, cudaFuncAttributeMaxDynamicSharedMemorySize, SMEM_ATTN);
    attn_kernel<<<dim3(SEQ / 64, L_TOT / SEQ, NH), 128, SMEM_ATTN>>>();

    // output projection: A[4096,2048] @ Wo[2048,2560] -> out fp32
    gemm_f16f32<<<dim3(HID / BN, L_TOT / BM), 256>>>(
        (const __half*)pA, (const __half*)pWo, out, L_TOT, HID, NH * HD, HID);
}

// round 3
// speedup vs baseline: 1.0330x; 1.0330x over previous
#include <cuda_runtime.h>
#include <cuda_fp16.h>
#include <cuda_bf16.h>
#include <cstdint>

#define L_TOT 4096
#define HID   2560
#define NH    8
#define NKV   4
#define HD    256
#define SEQ   1024
#define QKV_W 4096   // 2048 q + 1024 k + 1024 v columns

// ---------------- device scratch (no dynamic alloc allowed) ----------------
__device__ __half g_Xh [(size_t)L_TOT * HID];          // hidden fp16 [4096][2560]
__device__ __half g_WB [(size_t)HID * QKV_W];          // [2560][4096] packed Wq|Wk|Wv fp16
__device__ __half g_Woh[(size_t)(NH * HD) * HID];      // [2048][2560] Wo fp16
__device__ float  g_qkv[(size_t)L_TOT * QKV_W];        // fp32 pre-norm q|k|v
__device__ __half g_Q[(size_t)NH  * L_TOT * HD];       // [h][t][d], pre-scaled by 1/16
__device__ __half g_K[(size_t)NKV * L_TOT * HD];
__device__ __half g_V[(size_t)NKV * L_TOT * HD];
__device__ __half g_A[(size_t)L_TOT * NH * HD];        // attention output [t][h*HD+d]

// ---------------- PTX helpers ----------------
__device__ __forceinline__ uint32_t sptr(const void* p) {
    return static_cast<uint32_t>(__cvta_generic_to_shared(p));
}
__device__ __forceinline__ void ldsm_x4(uint32_t* r, const void* p) {
    uint32_t a = sptr(p);
    asm volatile("ldmatrix.sync.aligned.m8n8.x4.shared.b16 {%0,%1,%2,%3}, [%4];"
                 : "=r"(r[0]), "=r"(r[1]), "=r"(r[2]), "=r"(r[3]) : "r"(a));
}
__device__ __forceinline__ void ldsm_x4_t(uint32_t* r, const void* p) {
    uint32_t a = sptr(p);
    asm volatile("ldmatrix.sync.aligned.m8n8.x4.trans.shared.b16 {%0,%1,%2,%3}, [%4];"
                 : "=r"(r[0]), "=r"(r[1]), "=r"(r[2]), "=r"(r[3]) : "r"(a));
}
__device__ __forceinline__ void mma_16816(float* c, const uint32_t* a, const uint32_t* b) {
    asm volatile(
        "mma.sync.aligned.m16n8k16.row.col.f32.f16.f16.f32 "
        "{%0,%1,%2,%3}, {%4,%5,%6,%7}, {%8,%9}, {%0,%1,%2,%3};"
        : "+f"(c[0]), "+f"(c[1]), "+f"(c[2]), "+f"(c[3])
        : "r"(a[0]), "r"(a[1]), "r"(a[2]), "r"(a[3]), "r"(b[0]), "r"(b[1]));
}
__device__ __forceinline__ void cp16(void* s, const void* g) {
    uint32_t a = sptr(s);
    asm volatile("cp.async.cg.shared.global [%0], [%1], 16;" :: "r"(a), "l"(g));
}
__device__ __forceinline__ void cp_commit() { asm volatile("cp.async.commit_group;"); }

__device__ __forceinline__ uint32_t packh2(float a, float b) {
    __half2 h = __floats2half2_rn(a, b);
    return *reinterpret_cast<uint32_t*>(&h);
}
__device__ __forceinline__ float qmax(float v) {
    v = fmaxf(v, __shfl_xor_sync(0xffffffffu, v, 1));
    v = fmaxf(v, __shfl_xor_sync(0xffffffffu, v, 2));
    return v;
}
__device__ __forceinline__ float qsum(float v) {
    v += __shfl_xor_sync(0xffffffffu, v, 1);
    v += __shfl_xor_sync(0xffffffffu, v, 2);
    return v;
}

// ---------------- fp32 -> fp16 convert (vectorized by 4) ----------------
__global__ void f2h4_kernel(const float4* __restrict__ src, __half2* __restrict__ dst, int n4) {
    int i = blockIdx.x * blockDim.x + threadIdx.x;
    if (i >= n4) return;
    float4 v = src[i];
    dst[2 * i]     = __floats2half2_rn(v.x, v.y);
    dst[2 * i + 1] = __floats2half2_rn(v.z, v.w);
}

// ---------------- fp32 -> fp16 convert into strided (packed) destination ----------------
// src: [K][N] fp32 contiguous; dst row stride ldd (halves), column offset coloff
__global__ void f2h_pack(const float2* __restrict__ src, __half2* __restrict__ dst,
                         int N2, int total2, int ldd2, int coloff2) {
    int i = blockIdx.x * blockDim.x + threadIdx.x;
    if (i >= total2) return;
    int k = i / N2, n = i - k * N2;
    float2 v = src[i];
    dst[(size_t)k * ldd2 + coloff2 + n] = __floats2half2_rn(v.x, v.y);
}

// ---------------- fp16 GEMM: C(f32)[M,N] = A(f16)[M,K] * B(f16)[K,N] ----------------
// 128x128x64 tile, 3-stage cp.async pipeline, 8 warps (2x4), warp tile 64x32
#define BM 128
#define BN 128
#define BK 64
#define NSTG 3
#define AS_STRIDE (BK + 8)          // 72 halves
#define BS_STRIDE (BN + 8)          // 136 halves
#define AS_BYTES (BM * AS_STRIDE * 2)          // 18432
#define BS_BYTES (BK * BS_STRIDE * 2)          // 17408
#define STG_BYTES (AS_BYTES + BS_BYTES)        // 35840
#define GEMM_SMEM (NSTG * STG_BYTES)           // 107520

__global__ __launch_bounds__(256) void gemm_f16f32(
    const __half* __restrict__ A, const __half* __restrict__ B,
    float* __restrict__ C, int M, int N, int K, int ldc)
{
    extern __shared__ __align__(16) char dsm[];

    int tid = threadIdx.x;
    int warp = tid >> 5, lane = tid & 31;
    int wm = warp >> 2, wn = warp & 3;
    int bm = blockIdx.y * BM, bn = blockIdx.x * BN;
    int nkt = K / BK;

    float acc[4][4][4];
#pragma unroll
    for (int a = 0; a < 4; a++)
#pragma unroll
        for (int b = 0; b < 4; b++)
#pragma unroll
            for (int c = 0; c < 4; c++) acc[a][b][c] = 0.f;

    auto stageA = [&](int s) -> __half* {
        return reinterpret_cast<__half*>(dsm + (size_t)s * STG_BYTES);
    };
    auto stageB = [&](int s) -> __half* {
        return reinterpret_cast<__half*>(dsm + (size_t)s * STG_BYTES + AS_BYTES);
    };

    auto load_stage = [&](int kt) {
        int s = kt % NSTG;
        __half* As = stageA(s);
        __half* Bs = stageB(s);
        const __half* Ag = A + (size_t)bm * K + kt * BK;
        const __half* Bg = B + (size_t)(kt * BK) * N + bn;
#pragma unroll
        for (int i = 0; i < 4; i++) {            // A: 128 rows x 8 chunks of 16B
            int v = i * 256 + tid;
            int r = v >> 3, c = v & 7;
            cp16(As + r * AS_STRIDE + c * 8, Ag + (size_t)r * K + c * 8);
        }
#pragma unroll
        for (int i = 0; i < 4; i++) {            // B: 64 rows x 16 chunks of 16B
            int v = i * 256 + tid;
            int r = v >> 4, c = v & 15;
            cp16(Bs + r * BS_STRIDE + c * 8, Bg + (size_t)r * N + c * 8);
        }
        cp_commit();
    };

    load_stage(0); load_stage(1); load_stage(2);

    for (int kt = 0; kt < nkt; kt++) {
        asm volatile("cp.async.wait_group 2;");
        __syncthreads();

        int s = kt % NSTG;
        __half* As = stageA(s);
        __half* Bs = stageB(s);
#pragma unroll
        for (int kk = 0; kk < 4; kk++) {
            uint32_t af[4][4];
#pragma unroll
            for (int mi = 0; mi < 4; mi++)
                ldsm_x4(af[mi], As + (wm * 64 + mi * 16 + (lane & 15)) * AS_STRIDE
                                   + kk * 16 + (lane >> 4) * 8);
            uint32_t bf[2][4];
#pragma unroll
            for (int g = 0; g < 2; g++)
                ldsm_x4_t(bf[g], Bs + (kk * 16 + (lane & 15)) * BS_STRIDE
                                    + wn * 32 + g * 16 + (lane >> 4) * 8);
#pragma unroll
            for (int mi = 0; mi < 4; mi++)
#pragma unroll
                for (int ni = 0; ni < 4; ni++)
                    mma_16816(acc[mi][ni], af[mi], &bf[ni >> 1][(ni & 1) * 2]);
        }
        __syncthreads();

        if (kt + NSTG < nkt) load_stage(kt + NSTG);
        else cp_commit();   // keep group accounting uniform
    }

#pragma unroll
    for (int mi = 0; mi < 4; mi++)
#pragma unroll
        for (int ni = 0; ni < 4; ni++) {
            int r0 = bm + wm * 64 + mi * 16 + (lane >> 2);
            int c0 = bn + wn * 32 + ni * 8 + (lane & 3) * 2;
            float2 v0 = make_float2(acc[mi][ni][0], acc[mi][ni][1]);
            float2 v1 = make_float2(acc[mi][ni][2], acc[mi][ni][3]);
            *reinterpret_cast<float2*>(C + (size_t)r0 * ldc + c0)       = v0;
            *reinterpret_cast<float2*>(C + (size_t)(r0 + 8) * ldc + c0) = v1;
        }
}

// ---------------- RMSNorm + RoPE (warp per (token, head)) ----------------
__global__ __launch_bounds__(256) void normrope_kernel(
    const float* __restrict__ qkv, const float* __restrict__ cosb,
    const float* __restrict__ sinb, const float* __restrict__ qw,
    const float* __restrict__ kw)
{
    int gw = blockIdx.x * 8 + (threadIdx.x >> 5);
    int lane = threadIdx.x & 31;
    int t = gw / 12, hh = gw - t * 12;

    const float* src; const float* w; __half* dst; float sc;
    if (hh < 8) {
        src = qkv + (size_t)t * QKV_W + hh * HD;
        w = qw; dst = g_Q + ((size_t)hh * L_TOT + t) * HD;
        sc = 0.0625f;   // fold SCALING = 256^-0.5
    } else {
        int kvh = hh - 8;
        src = qkv + (size_t)t * QKV_W + 2048 + kvh * HD;
        w = kw; dst = g_K + ((size_t)kvh * L_TOT + t) * HD;
        sc = 1.0f;
    }

    int j = lane * 4;
    float4 x1 = *reinterpret_cast<const float4*>(src + j);
    float4 x2 = *reinterpret_cast<const float4*>(src + 128 + j);

    float ss = x1.x * x1.x + x1.y * x1.y + x1.z * x1.z + x1.w * x1.w
             + x2.x * x2.x + x2.y * x2.y + x2.z * x2.z + x2.w * x2.w;
#pragma unroll
    for (int o = 16; o; o >>= 1) ss += __shfl_xor_sync(0xffffffffu, ss, o);
    float r = rsqrtf(ss * (1.0f / 256.0f) + 1e-6f);

    float4 w1 = *reinterpret_cast<const float4*>(w + j);
    float4 w2 = *reinterpret_cast<const float4*>(w + 128 + j);
    float4 c1 = *reinterpret_cast<const float4*>(cosb + (size_t)t * HD + j);
    float4 c2 = *reinterpret_cast<const float4*>(cosb + (size_t)t * HD + 128 + j);
    float4 s1 = *reinterpret_cast<const float4*>(sinb + (size_t)t * HD + j);
    float4 s2 = *reinterpret_cast<const float4*>(sinb + (size_t)t * HD + 128 + j);

    float n1[4] = { x1.x * r * (1.f + w1.x), x1.y * r * (1.f + w1.y),
                    x1.z * r * (1.f + w1.z), x1.w * r * (1.f + w1.w) };
    float n2[4] = { x2.x * r * (1.f + w2.x), x2.y * r * (1.f + w2.y),
                    x2.z * r * (1.f + w2.z), x2.w * r * (1.f + w2.w) };
    float cA[4] = { c1.x, c1.y, c1.z, c1.w }, cB[4] = { c2.x, c2.y, c2.z, c2.w };
    float sA[4] = { s1.x, s1.y, s1.z, s1.w }, sB[4] = { s2.x, s2.y, s2.z, s2.w };

    __half2 o1[2], o2[2];
#pragma unroll
    for (int i = 0; i < 4; i++) {
        float lo = (n1[i] * cA[i] - n2[i] * sA[i]) * sc;   // d = j+i
        float hi = (n2[i] * cB[i] + n1[i] * sB[i]) * sc;   // d = j+i+128
        reinterpret_cast<__half*>(o1)[i] = __float2half_rn(lo);
        reinterpret_cast<__half*>(o2)[i] = __float2half_rn(hi);
    }
    *reinterpret_cast<__half2*>(dst + j)       = o1[0];
    *reinterpret_cast<__half2*>(dst + j + 2)   = o1[1];
    *reinterpret_cast<__half2*>(dst + 128 + j)     = o2[0];
    *reinterpret_cast<__half2*>(dst + 128 + j + 2) = o2[1];
}

// ---------------- V convert fp32 -> fp16 head-major ----------------
__global__ void vconv_kernel(const float* __restrict__ qkv) {
    int i = blockIdx.x * blockDim.x + threadIdx.x;   // over L_TOT*512 half2
    if (i >= L_TOT * 512) return;
    int t = i >> 9, c = (i & 511) * 2;
    int kvh = c >> 8, d = c & 255;
    float2 v = *reinterpret_cast<const float2*>(qkv + (size_t)t * QKV_W + 3072 + c);
    *reinterpret_cast<__half2*>(g_V + ((size_t)kvh * L_TOT + t) * HD + d) =
        __floats2half2_rn(v.x, v.y);
}

// ---------------- flash attention: CTA = (qtile, seq, head), 4 warps ----------------
// Q tile [64][264] + double-buffered K,V tiles
#define ATT_STRIDE 264
#define ATT_TILE (64 * ATT_STRIDE)             // halves per tile
#define SMEM_ATTN ((1 + 4) * ATT_TILE * 2)     // Q + 2x(K,V)  = 168960 bytes

__global__ __launch_bounds__(128) void attn_kernel() {
    extern __shared__ __half sm[];
    __half* sQ = sm;
    __half* sK[2] = { sm + ATT_TILE,     sm + 3 * ATT_TILE };
    __half* sV[2] = { sm + 2 * ATT_TILE, sm + 4 * ATT_TILE };

    int tid = threadIdx.x, warp = tid >> 5, lane = tid & 31;
    int qt = blockIdx.x, seq = blockIdx.y, h = blockIdx.z;
    int kvh = h >> 1;

    const __half* Qg = g_Q + ((size_t)h * L_TOT + seq * SEQ + qt * 64) * HD;
    const __half* Kg = g_K + ((size_t)kvh * L_TOT + seq * SEQ) * HD;
    const __half* Vg = g_V + ((size_t)kvh * L_TOT + seq * SEQ) * HD;

#pragma unroll
    for (int i = 0; i < 16; i++) {
        int v = i * 128 + tid, r = v >> 5, cv = v & 31;
        cp16(&sQ[r * ATT_STRIDE + cv * 8], Qg + (size_t)r * HD + cv * 8);
    }
    cp_commit();

    auto loadKV = [&](int kt, int buf) {
#pragma unroll
        for (int i = 0; i < 16; i++) {
            int v = i * 128 + tid, r = v >> 5, cv = v & 31;
            cp16(&sK[buf][r * ATT_STRIDE + cv * 8], Kg + (size_t)(kt * 64 + r) * HD + cv * 8);
            cp16(&sV[buf][r * ATT_STRIDE + cv * 8], Vg + (size_t)(kt * 64 + r) * HD + cv * 8);
        }
        cp_commit();
    };
    loadKV(0, 0);

    float o[32][4];
#pragma unroll
    for (int nt = 0; nt < 32; nt++)
#pragma unroll
        for (int c = 0; c < 4; c++) o[nt][c] = 0.f;
    float m0 = -1e30f, m1 = -1e30f, l0 = 0.f, l1 = 0.f;

    for (int kt = 0; kt <= qt; kt++) {
        int buf = kt & 1;
        if (kt < qt) {
            loadKV(kt + 1, buf ^ 1);
            asm volatile("cp.async.wait_group 1;");
        } else {
            asm volatile("cp.async.wait_group 0;");
        }
        __syncthreads();

        float s[8][4];
#pragma unroll
        for (int nt = 0; nt < 8; nt++)
#pragma unroll
            for (int c = 0; c < 4; c++) s[nt][c] = 0.f;

#pragma unroll
        for (int kc = 0; kc < 16; kc++) {
            uint32_t af[4];
            ldsm_x4(af, &sQ[(warp * 16 + (lane & 15)) * ATT_STRIDE + kc * 16 + (lane >> 4) * 8]);
#pragma unroll
            for (int g = 0; g < 4; g++) {
                uint32_t bf[4];
                ldsm_x4(bf, &sK[buf][(g * 16 + (lane & 15)) * ATT_STRIDE + kc * 16 + (lane >> 4) * 8]);
                uint32_t b0[2] = { bf[0], bf[2] };
                uint32_t b1[2] = { bf[1], bf[3] };
                mma_16816(s[2 * g],     af, b0);
                mma_16816(s[2 * g + 1], af, b1);
            }
        }

        if (kt == qt) {
            int r0 = warp * 16 + (lane >> 2);
#pragma unroll
            for (int nt = 0; nt < 8; nt++) {
                int c = nt * 8 + (lane & 3) * 2;
                if (c     > r0)     s[nt][0] = -1e30f;
                if (c + 1 > r0)     s[nt][1] = -1e30f;
                if (c     > r0 + 8) s[nt][2] = -1e30f;
                if (c + 1 > r0 + 8) s[nt][3] = -1e30f;
            }
        }

        float mx0 = -1e30f, mx1 = -1e30f;
#pragma unroll
        for (int nt = 0; nt < 8; nt++) {
            mx0 = fmaxf(mx0, fmaxf(s[nt][0], s[nt][1]));
            mx1 = fmaxf(mx1, fmaxf(s[nt][2], s[nt][3]));
        }
        mx0 = qmax(mx0); mx1 = qmax(mx1);
        float nm0 = fmaxf(m0, mx0), nm1 = fmaxf(m1, mx1);
        float a0 = __expf(m0 - nm0), a1 = __expf(m1 - nm1);
        float sum0 = 0.f, sum1 = 0.f;
#pragma unroll
        for (int nt = 0; nt < 8; nt++) {
            s[nt][0] = __expf(s[nt][0] - nm0);
            s[nt][1] = __expf(s[nt][1] - nm0);
            s[nt][2] = __expf(s[nt][2] - nm1);
            s[nt][3] = __expf(s[nt][3] - nm1);
            sum0 += s[nt][0] + s[nt][1];
            sum1 += s[nt][2] + s[nt][3];
        }
        sum0 = qsum(sum0); sum1 = qsum(sum1);
        l0 = l0 * a0 + sum0; l1 = l1 * a1 + sum1;
        m0 = nm0; m1 = nm1;
#pragma unroll
        for (int nt = 0; nt < 32; nt++) {
            o[nt][0] *= a0; o[nt][1] *= a0;
            o[nt][2] *= a1; o[nt][3] *= a1;
        }

#pragma unroll
        for (int j = 0; j < 4; j++) {
            uint32_t af2[4];
            af2[0] = packh2(s[2 * j][0],     s[2 * j][1]);
            af2[1] = packh2(s[2 * j][2],     s[2 * j][3]);
            af2[2] = packh2(s[2 * j + 1][0], s[2 * j + 1][1]);
            af2[3] = packh2(s[2 * j + 1][2], s[2 * j + 1][3]);
#pragma unroll
            for (int g = 0; g < 16; g++) {
                uint32_t bf[4];
                ldsm_x4_t(bf, &sV[buf][(j * 16 + (lane & 15)) * ATT_STRIDE + g * 16 + (lane >> 4) * 8]);
                mma_16816(o[2 * g],     af2, &bf[0]);
                mma_16816(o[2 * g + 1], af2, &bf[2]);
            }
        }
        __syncthreads();
    }

    float i0 = 1.f / l0, i1 = 1.f / l1;
    int row = seq * SEQ + qt * 64 + warp * 16 + (lane >> 2);
    __half* Ob0 = g_A + (size_t)row * (NH * HD) + h * HD;
    __half* Ob1 = g_A + (size_t)(row + 8) * (NH * HD) + h * HD;
#pragma unroll
    for (int nt = 0; nt < 32; nt++) {
        int c = nt * 8 + (lane & 3) * 2;
        *reinterpret_cast<__half2*>(Ob0 + c) = __floats2half2_rn(o[nt][0] * i0, o[nt][1] * i0);
        *reinterpret_cast<__half2*>(Ob1 + c) = __floats2half2_rn(o[nt][2] * i1, o[nt][3] * i1);
    }
}

// ---------------- launch ----------------
extern "C" void kernel_launch(void* const* d_in, const int* in_sizes, int n_in,
                              void* d_out, int out_size) {
    const float* X    = (const float*)d_in[0];
    const float* cosb = (const float*)d_in[1];
    const float* sinb = (const float*)d_in[2];
    const float* Wq   = (const float*)d_in[3];
    const float* Wk   = (const float*)d_in[4];
    const float* Wv   = (const float*)d_in[5];
    const float* Wo   = (const float*)d_in[6];
    const float* qw   = (const float*)d_in[7];
    const float* kw   = (const float*)d_in[8];
    float* out = (float*)d_out;

    void *pXh, *pWB, *pWo, *pqkv, *pA;
    cudaGetSymbolAddress(&pXh,  g_Xh);
    cudaGetSymbolAddress(&pWB,  g_WB);
    cudaGetSymbolAddress(&pWo,  g_Woh);
    cudaGetSymbolAddress(&pqkv, g_qkv);
    cudaGetSymbolAddress(&pA,   g_A);

    // X convert
    {
        int n4 = (L_TOT * HID) / 4;
        f2h4_kernel<<<(n4 + 255) / 256, 256>>>((const float4*)X, (__half2*)pXh, n4);
    }
    // pack Wq|Wk|Wv into g_WB [2560][4096] (fp16), columns 0..2047 | 2048..3071 | 3072..4095
    {
        int t2;
        t2 = HID * 2048 / 2;
        f2h_pack<<<(t2 + 255) / 256, 256>>>((const float2*)Wq, (__half2*)pWB,
                                            1024, t2, QKV_W / 2, 0);
        t2 = HID * 1024 / 2;
        f2h_pack<<<(t2 + 255) / 256, 256>>>((const float2*)Wk, (__half2*)pWB,
                                            512, t2, QKV_W / 2, 1024);
        f2h_pack<<<(t2 + 255) / 256, 256>>>((const float2*)Wv, (__half2*)pWB,
                                            512, t2, QKV_W / 2, 1536);
    }
    // Wo convert (no transpose; B stays [K=2048][N=2560])
    {
        int n4 = (NH * HD * HID) / 4;
        f2h4_kernel<<<(n4 + 255) / 256, 256>>>((const float4*)Wo, (__half2*)pWo, n4);
    }

    cudaFuncSetAttribute(gemm_f16f32, cudaFuncAttributeMaxDynamicSharedMemorySize, GEMM_SMEM);

    // fused QKV projection: X[4096,2560] @ WB[2560,4096] -> g_qkv
    gemm_f16f32<<<dim3(QKV_W / BN, L_TOT / BM), 256, GEMM_SMEM>>>(
        (const __half*)pXh, (const __half*)pWB, (float*)pqkv, L_TOT, QKV_W, HID, QKV_W);

    normrope_kernel<<<L_TOT * 12 / 8, 256>>>((const float*)pqkv, cosb, sinb, qw, kw);
    vconv_kernel<<<(L_TOT * 512 + 255) / 256, 256>>>((const float*)pqkv);

    cudaFuncSetAttribute(attn_kernel, cudaFuncAttributeMaxDynamicSharedMemorySize, SMEM_ATTN);
    attn_kernel<<<dim3(SEQ / 64, L_TOT / SEQ, NH), 128, SMEM_ATTN>>>();

    // output projection: g_A[4096,2048] @ Wo[2048,2560] -> out
    gemm_f16f32<<<dim3(HID / BN, L_TOT / BM), 256, GEMM_SMEM>>>(
        (const __half*)pA, (const __half*)pWo, out, L_TOT, HID, NH * HD, HID);
}